// round 4
// baseline (speedup 1.0000x reference)
#include <cuda_runtime.h>
#include <cstdint>
#include <cstdio>

// PoolingRetriever collapses analytically:
//   softmax over a singleton axis == 1.0, so xi == 1 through all 5 steps,
//   out == v  =>  out = (x @ Wv.T + bv) @ Wo.T + bo
// R3: cp.async double-buffered pipeline. Weights pre-converted to tf32 once
// (device-global scratch); x staged raw via LDGSTS, cvt folded into A-frag load.

#define DIM      768
#define HH       64
#define TILE_M   128
#define NTHREADS 256
#define STRD     68                       // padded stride: conflict-free frags, 16B-aligned
#define X_WORDS  (TILE_M * STRD)          // 8704 per buffer
#define W_WORDS  (HH * STRD)              // 4352 per buffer
#define SMEM_WORDS (2 * X_WORDS + 2 * W_WORDS + 64)   // 26176
#define SMEM_BYTES (SMEM_WORDS * 4)                   // 104704
#define NCH1     12                       // stage-1 chunks
#define NCH      24                       // total pipeline chunks

__device__ uint32_t g_Wvt[HH * DIM];      // Wv as tf32, layout [64][768]
__device__ uint32_t g_Wot[DIM * HH];      // Wo as tf32, layout [768][64]

__device__ __forceinline__ uint32_t f2tf32(float f) {
    uint32_t r;
    asm("cvt.rna.tf32.f32 %0, %1;" : "=r"(r) : "f"(f));
    return r;
}

__device__ __forceinline__ void cp16(void* sdst, const void* gsrc) {
    uint32_t s = (uint32_t)__cvta_generic_to_shared(sdst);
    asm volatile("cp.async.ca.shared.global [%0], [%1], 16;\n" :: "r"(s), "l"(gsrc));
}

__device__ __forceinline__ void mma8(float d[4], const uint32_t a[4], const uint32_t b[2]) {
    asm volatile(
        "mma.sync.aligned.m16n8k8.row.col.f32.tf32.tf32.f32 "
        "{%0,%1,%2,%3}, {%4,%5,%6,%7}, {%8,%9}, {%0,%1,%2,%3};\n"
        : "+f"(d[0]), "+f"(d[1]), "+f"(d[2]), "+f"(d[3])
        : "r"(a[0]), "r"(a[1]), "r"(a[2]), "r"(a[3]), "r"(b[0]), "r"(b[1]));
}

// Prologue kernel: convert Wv and Wo to tf32 once (400 KB total, ~2us).
__global__ void convert_weights_kernel(const float* __restrict__ Wv,
                                       const float* __restrict__ Wo) {
    int idx = blockIdx.x * blockDim.x + threadIdx.x;   // over 12288 float4 each
    if (idx < (HH * DIM) / 4) {
        float4 v = ((const float4*)Wv)[idx];
        uint4 o = make_uint4(f2tf32(v.x), f2tf32(v.y), f2tf32(v.z), f2tf32(v.w));
        ((uint4*)g_Wvt)[idx] = o;
        v = ((const float4*)Wo)[idx];
        o = make_uint4(f2tf32(v.x), f2tf32(v.y), f2tf32(v.z), f2tf32(v.w));
        ((uint4*)g_Wot)[idx] = o;
    }
}

__global__ __launch_bounds__(NTHREADS, 2)
void pooling_retriever_kernel(const float* __restrict__ x,
                              const float* __restrict__ bv,
                              const float* __restrict__ bo,
                              float* __restrict__ out) {
    extern __shared__ uint32_t smem[];
    // layout: Xraw[2] (raw f32 for x; buf0 reused as tf32 T), Ws[2] (tf32 W), bias
    uint32_t* Ws0   = smem + 2 * X_WORDS;
    float*    bias_s = (float*)(smem + 2 * X_WORDS + 2 * W_WORDS);

    const int tid  = threadIdx.x;
    const int warp = tid >> 5;
    const int lane = tid & 31;
    const int gid  = lane >> 2;
    const int t4   = lane & 3;
    const int m0   = blockIdx.x * TILE_M;
    const int wrow = warp * 16;

    // ---- pipeline chunk issue: k<12 -> x chunk + Wv chunk; k>=12 -> Wo chunk ----
    auto issue_chunk = [&](int k) {
        uint32_t* wb = Ws0 + (k & 1) * W_WORDS;
        if (k < NCH1) {
            const int kc = k * 64;
            uint32_t* xb = smem + (k & 1) * X_WORDS;
            #pragma unroll
            for (int i = 0; i < 8; i++) {                 // 128x64 f32 = 2048 float4
                int idx = tid + i * NTHREADS;
                int r  = idx >> 4;
                int c4 = (idx & 15) << 2;
                cp16(xb + r * STRD + c4, x + (size_t)(m0 + r) * DIM + kc + c4);
            }
            #pragma unroll
            for (int i = 0; i < 4; i++) {                 // 64x64 tf32
                int idx = tid + i * NTHREADS;
                int r  = idx >> 4;
                int c4 = (idx & 15) << 2;
                cp16(wb + r * STRD + c4, g_Wvt + (size_t)r * DIM + kc + c4);
            }
        } else {
            const int nc = (k - NCH1) * 64;
            #pragma unroll
            for (int i = 0; i < 4; i++) {                 // 64x64 tf32 (Wo rows nc..nc+63)
                int idx = tid + i * NTHREADS;
                int r  = idx >> 4;
                int c4 = (idx & 15) << 2;
                cp16(wb + r * STRD + c4, g_Wot + (size_t)(nc + r) * HH + c4);
            }
        }
        asm volatile("cp.async.commit_group;\n");
    };

    // prologue
    issue_chunk(0);
    if (tid < HH) bias_s[tid] = bv[tid];

    // ---------------- Stage 1: T = x @ Wv.T + bv ----------------
    float acc[8][4];
    #pragma unroll
    for (int nb = 0; nb < 8; nb++)
        #pragma unroll
        for (int i = 0; i < 4; i++) acc[nb][i] = 0.f;

    for (int k = 0; k < NCH1; k++) {
        __syncthreads();                       // compute of k-1 done -> buf (k+1)&1 free
        issue_chunk(k + 1);                    // k+1 <= 12 always here
        asm volatile("cp.async.wait_group 1;\n");
        __syncthreads();                       // chunk k visible to all warps

        const float*    xb = (const float*)(smem + (k & 1) * X_WORDS);
        const uint32_t* wb = Ws0 + (k & 1) * W_WORDS;
        #pragma unroll
        for (int ks = 0; ks < 8; ks++) {
            const float* r0p = xb + (wrow + gid)     * STRD + ks * 8;
            const float* r1p = xb + (wrow + gid + 8) * STRD + ks * 8;
            uint32_t a[4];
            a[0] = f2tf32(r0p[t4]);     a[1] = f2tf32(r1p[t4]);
            a[2] = f2tf32(r0p[t4 + 4]); a[3] = f2tf32(r1p[t4 + 4]);
            #pragma unroll
            for (int nb = 0; nb < 8; nb++) {
                uint32_t b[2];
                const uint32_t* bp = wb + (nb * 8 + gid) * STRD + ks * 8;
                b[0] = bp[t4]; b[1] = bp[t4 + 4];
                mma8(acc[nb], a, b);
            }
        }
    }

    // Write T = acc + bv as tf32 into Xraw buf0 (each warp its own 16 rows).
    // Safe: chunk >= 12 has no x-part in flight; buf0 last read at chunk 10 (done).
    uint32_t* Ts = smem;
    #pragma unroll
    for (int nb = 0; nb < 8; nb++) {
        int c = nb * 8 + 2 * t4;
        float b0 = bias_s[c], b1 = bias_s[c + 1];
        uint32_t* d0 = Ts + (wrow + gid)     * STRD + c;
        uint32_t* d1 = Ts + (wrow + gid + 8) * STRD + c;
        d0[0] = f2tf32(acc[nb][0] + b0);
        d0[1] = f2tf32(acc[nb][1] + b1);
        d1[0] = f2tf32(acc[nb][2] + b0);
        d1[1] = f2tf32(acc[nb][3] + b1);
    }
    __syncwarp();

    uint32_t ta[8][4];
    #pragma unroll
    for (int ks = 0; ks < 8; ks++) {
        const uint32_t* r0p = Ts + (wrow + gid)     * STRD + ks * 8;
        const uint32_t* r1p = Ts + (wrow + gid + 8) * STRD + ks * 8;
        ta[ks][0] = r0p[t4];     ta[ks][1] = r1p[t4];
        ta[ks][2] = r0p[t4 + 4]; ta[ks][3] = r1p[t4 + 4];
    }

    // ---------------- Stage 2: out = T @ Wo.T + bo ----------------
    for (int k = NCH1; k < NCH; k++) {
        const int nc = (k - NCH1) * 64;
        __syncthreads();                       // prev epilogue done -> buffer + bias free
        if (tid < HH) bias_s[tid] = bo[nc + tid];
        if (k + 1 < NCH) {
            issue_chunk(k + 1);
            asm volatile("cp.async.wait_group 1;\n");
        } else {
            asm volatile("cp.async.wait_group 0;\n");
        }
        __syncthreads();                       // chunk k + bias visible

        const uint32_t* wb = Ws0 + (k & 1) * W_WORDS;
        float oacc[8][4];
        #pragma unroll
        for (int nb = 0; nb < 8; nb++)
            #pragma unroll
            for (int i = 0; i < 4; i++) oacc[nb][i] = 0.f;

        #pragma unroll
        for (int ks = 0; ks < 8; ks++) {
            #pragma unroll
            for (int nb = 0; nb < 8; nb++) {
                uint32_t b[2];
                const uint32_t* bp = wb + (nb * 8 + gid) * STRD + ks * 8;
                b[0] = bp[t4]; b[1] = bp[t4 + 4];
                mma8(oacc[nb], ta[ks], b);
            }
        }
        #pragma unroll
        for (int nb = 0; nb < 8; nb++) {
            int c = nb * 8 + 2 * t4;
            float b0 = bias_s[c], b1 = bias_s[c + 1];
            float2 v0 = make_float2(oacc[nb][0] + b0, oacc[nb][1] + b1);
            float2 v1 = make_float2(oacc[nb][2] + b0, oacc[nb][3] + b1);
            *(float2*)(out + (size_t)(m0 + wrow + gid)     * DIM + nc + c) = v0;
            *(float2*)(out + (size_t)(m0 + wrow + gid + 8) * DIM + nc + c) = v1;
        }
    }
}

extern "C" void kernel_launch(void* const* d_in, const int* in_sizes, int n_in,
                              void* d_out, int out_size) {
    // metadata order: x, q_state, Wq, bq, Wk, bk, Wv, bv, Wo, bo
    const float* x  = (const float*)d_in[0];
    const float* Wv = (const float*)d_in[6];
    const float* bv = (const float*)d_in[7];
    const float* Wo = (const float*)d_in[8];
    const float* bo = (const float*)d_in[9];
    float* out = (float*)d_out;

    const int n_rows = in_sizes[0] / DIM;      // 65536
    const int grid   = n_rows / TILE_M;        // 512

    convert_weights_kernel<<<48, 256>>>(Wv, Wo);

    cudaFuncSetAttribute(pooling_retriever_kernel,
                         cudaFuncAttributeMaxDynamicSharedMemorySize, SMEM_BYTES);
    pooling_retriever_kernel<<<grid, NTHREADS, SMEM_BYTES>>>(x, bv, bo, out);
}

// round 5
// speedup vs baseline: 1.0285x; 1.0285x over previous
#include <cuda_runtime.h>
#include <cstdint>

// out = (x @ Wv.T + bv) @ Wo.T + bo   (softmax over singleton axis == 1)
// R4: LDS-bound fix. Weights pre-permuted into per-lane fragment order
// (80B lane stride -> conflict-free LDS.128), m32 warp tiles halve B traffic,
// cp.async depth-2 pipeline for x and W chunks.

#define DIM      768
#define HH       64
#define TILE_M   128
#define NTHREADS 128                      // 4 warps, m32 rows per warp
#define XSTR     68                       // x smem row stride (words), conflict-free
#define XW       (TILE_M * XSTR)          // 8704 words per x buffer
#define WCH      (8 * 32 * 20)            // 5120 words per W chunk (frag order, padded)
#define SMEM_WORDS (2 * XW + 2 * WCH + 64)
#define SMEM_BYTES (SMEM_WORDS * 4)       // 110848
#define NCH1     12
#define NCH      24

__device__ uint32_t g_Wfrag[NCH * WCH];   // 24 chunks x 5120 words = 480 KB

__device__ __forceinline__ uint32_t f2tf32(float f) {
    uint32_t r;
    asm("cvt.rna.tf32.f32 %0, %1;" : "=r"(r) : "f"(f));
    return r;
}

__device__ __forceinline__ void cp16(void* sdst, const void* gsrc) {
    uint32_t s = (uint32_t)__cvta_generic_to_shared(sdst);
    asm volatile("cp.async.ca.shared.global [%0], [%1], 16;\n" :: "r"(s), "l"(gsrc));
}

__device__ __forceinline__ void mma8(float d[4], const uint32_t a[4], uint32_t b0, uint32_t b1) {
    asm volatile(
        "mma.sync.aligned.m16n8k8.row.col.f32.tf32.tf32.f32 "
        "{%0,%1,%2,%3}, {%4,%5,%6,%7}, {%8,%9}, {%0,%1,%2,%3};\n"
        : "+f"(d[0]), "+f"(d[1]), "+f"(d[2]), "+f"(d[3])
        : "r"(a[0]), "r"(a[1]), "r"(a[2]), "r"(a[3]), "r"(b0), "r"(b1));
}

// Prologue: permute Wv/Wo into per-lane fragment order, tf32-converted.
// word layout: [(c*8+nb)*32 + lane]*20 + w,  w = ks*2+j (16 real words/lane).
// value = W[n = nb*8 + (lane>>2)][k = ks*8 + (lane&3) + 4*j]  within chunk c.
__global__ void convert_weights_kernel(const float* __restrict__ Wv,
                                       const float* __restrict__ Wo) {
    int idx = blockIdx.x * blockDim.x + threadIdx.x;   // over 24*8*32*16 = 98304
    if (idx >= NCH * 8 * 32 * 16) return;
    int w  = idx & 15;
    int l  = (idx >> 4) & 31;
    int nb = (idx >> 9) & 7;
    int c  = idx >> 12;
    int gid = l >> 2, t4 = l & 3;
    int ks = w >> 1, j = w & 1;
    int kk = ks * 8 + t4 + 4 * j;
    int n  = nb * 8 + gid;
    float v;
    if (c < NCH1) v = Wv[(size_t)n * DIM + c * 64 + kk];          // Wv [64][768]
    else          v = Wo[(size_t)((c - NCH1) * 64 + n) * HH + kk]; // Wo [768][64]
    g_Wfrag[((size_t)(c * 8 + nb) * 32 + l) * 20 + w] = f2tf32(v);
}

__global__ __launch_bounds__(NTHREADS, 2)
void pooling_retriever_kernel(const float* __restrict__ x,
                              const float* __restrict__ bv,
                              const float* __restrict__ bo,
                              float* __restrict__ out) {
    extern __shared__ uint32_t smem[];
    uint32_t* Wsm   = smem + 2 * XW;
    float*    bias_s = (float*)(smem + 2 * XW + 2 * WCH);

    const int tid  = threadIdx.x;
    const int warp = tid >> 5;
    const int lane = tid & 31;
    const int gid  = lane >> 2;
    const int t4   = lane & 3;
    const int m0   = blockIdx.x * TILE_M;
    const int wrow = warp * 32;            // 32 rows per warp

    auto issue_chunk = [&](int k) {
        uint32_t* wb = Wsm + (k & 1) * WCH;
        if (k < NCH1) {
            const int kc = k * 64;
            float* xb = (float*)(smem + (k & 1) * XW);
            #pragma unroll
            for (int i = 0; i < 16; i++) {              // 128x64 f32 = 2048 float4
                int idx = tid + i * NTHREADS;
                int r  = idx >> 4;
                int c4 = (idx & 15) << 2;
                cp16(xb + r * XSTR + c4, x + (size_t)(m0 + r) * DIM + kc + c4);
            }
        }
        const uint32_t* gsrc = g_Wfrag + (size_t)k * WCH;
        #pragma unroll
        for (int i = 0; i < 10; i++) {                  // 5120 words = 1280 float4
            int u = tid + i * NTHREADS;
            cp16(wb + u * 4, gsrc + u * 4);
        }
        asm volatile("cp.async.commit_group;\n");
    };

    issue_chunk(0);
    if (tid < HH) bias_s[tid] = bv[tid];

    // ---------------- Stage 1: T = x @ Wv.T + bv  (128 x 64) ----------------
    float acc[2][8][4];
    #pragma unroll
    for (int mt = 0; mt < 2; mt++)
        #pragma unroll
        for (int nb = 0; nb < 8; nb++)
            #pragma unroll
            for (int i = 0; i < 4; i++) acc[mt][nb][i] = 0.f;

    for (int k = 0; k < NCH1; k++) {
        __syncthreads();                   // compute k-1 done -> buffers (k+1)&1 free
        issue_chunk(k + 1);                // k==11 prefetches first Wo chunk
        asm volatile("cp.async.wait_group 1;\n");
        __syncthreads();                   // chunk k visible

        const float*    xb = (const float*)(smem + (k & 1) * XW);
        const uint32_t* wb = Wsm + (k & 1) * WCH;

        uint32_t a[2][8][4];               // A fragments for this chunk
        #pragma unroll
        for (int mt = 0; mt < 2; mt++) {
            int r0 = wrow + mt * 16 + gid;
            #pragma unroll
            for (int ks = 0; ks < 8; ks++) {
                const float* p0 = xb + r0 * XSTR + ks * 8;
                const float* p1 = p0 + 8 * XSTR;
                a[mt][ks][0] = f2tf32(p0[t4]);
                a[mt][ks][1] = f2tf32(p1[t4]);
                a[mt][ks][2] = f2tf32(p0[t4 + 4]);
                a[mt][ks][3] = f2tf32(p1[t4 + 4]);
            }
        }
        #pragma unroll
        for (int nb = 0; nb < 8; nb++) {
            const uint4* bp = (const uint4*)(wb + (nb * 32 + lane) * 20);
            uint4 B0 = bp[0], B1 = bp[1], B2 = bp[2], B3 = bp[3];
            #pragma unroll
            for (int ks = 0; ks < 8; ks++) {
                uint4 Bq = (ks >> 1) == 0 ? B0 : (ks >> 1) == 1 ? B1 : (ks >> 1) == 2 ? B2 : B3;
                uint32_t b0 = (ks & 1) ? Bq.z : Bq.x;
                uint32_t b1 = (ks & 1) ? Bq.w : Bq.y;
                mma8(acc[0][nb], a[0][ks], b0, b1);
                mma8(acc[1][nb], a[1][ks], b0, b1);
            }
        }
    }

    // Write T = acc + bv into x buf0 as tf32 (each warp its own 32 rows).
    // x buf0 last read at chunk 10 (done); chunks >= 12 never touch x buffers.
    uint32_t* Ts = smem;
    #pragma unroll
    for (int mt = 0; mt < 2; mt++) {
        #pragma unroll
        for (int nb = 0; nb < 8; nb++) {
            int c = nb * 8 + 2 * t4;
            float b0 = bias_s[c], b1 = bias_s[c + 1];
            uint32_t* d0 = Ts + (wrow + mt * 16 + gid)     * XSTR + c;
            uint32_t* d1 = d0 + 8 * XSTR;
            d0[0] = f2tf32(acc[mt][nb][0] + b0);
            d0[1] = f2tf32(acc[mt][nb][1] + b1);
            d1[0] = f2tf32(acc[mt][nb][2] + b0);
            d1[1] = f2tf32(acc[mt][nb][3] + b1);
        }
    }
    __syncwarp();

    uint32_t ta[2][8][4];                  // persistent stage-2 A fragments
    #pragma unroll
    for (int mt = 0; mt < 2; mt++) {
        int r0 = wrow + mt * 16 + gid;
        #pragma unroll
        for (int ks = 0; ks < 8; ks++) {
            const uint32_t* p0 = Ts + r0 * XSTR + ks * 8;
            const uint32_t* p1 = p0 + 8 * XSTR;
            ta[mt][ks][0] = p0[t4];     ta[mt][ks][1] = p1[t4];
            ta[mt][ks][2] = p0[t4 + 4]; ta[mt][ks][3] = p1[t4 + 4];
        }
    }

    // ---------------- Stage 2: out = T @ Wo.T + bo  (128 x 768) ----------------
    for (int k = NCH1; k < NCH; k++) {
        const int nc = (k - NCH1) * 64;
        __syncthreads();                   // prev epilogue done (bias + buffer free)
        if (tid < HH) bias_s[tid] = bo[nc + tid];
        if (k + 1 < NCH) {
            issue_chunk(k + 1);
            asm volatile("cp.async.wait_group 1;\n");
        } else {
            asm volatile("cp.async.wait_group 0;\n");
        }
        __syncthreads();                   // chunk k + bias visible

        const uint32_t* wb = Wsm + (k & 1) * WCH;
        float oacc[2][8][4];
        #pragma unroll
        for (int mt = 0; mt < 2; mt++)
            #pragma unroll
            for (int nb = 0; nb < 8; nb++)
                #pragma unroll
                for (int i = 0; i < 4; i++) oacc[mt][nb][i] = 0.f;

        #pragma unroll
        for (int nb = 0; nb < 8; nb++) {
            const uint4* bp = (const uint4*)(wb + (nb * 32 + lane) * 20);
            uint4 B0 = bp[0], B1 = bp[1], B2 = bp[2], B3 = bp[3];
            #pragma unroll
            for (int ks = 0; ks < 8; ks++) {
                uint4 Bq = (ks >> 1) == 0 ? B0 : (ks >> 1) == 1 ? B1 : (ks >> 1) == 2 ? B2 : B3;
                uint32_t b0 = (ks & 1) ? Bq.z : Bq.x;
                uint32_t b1 = (ks & 1) ? Bq.w : Bq.y;
                mma8(oacc[0][nb], ta[0][ks], b0, b1);
                mma8(oacc[1][nb], ta[1][ks], b0, b1);
            }
        }
        #pragma unroll
        for (int mt = 0; mt < 2; mt++) {
            #pragma unroll
            for (int nb = 0; nb < 8; nb++) {
                int c = nb * 8 + 2 * t4;
                float b0 = bias_s[c], b1 = bias_s[c + 1];
                float2 v0 = make_float2(oacc[mt][nb][0] + b0, oacc[mt][nb][1] + b1);
                float2 v1 = make_float2(oacc[mt][nb][2] + b0, oacc[mt][nb][3] + b1);
                size_t r0 = (size_t)(m0 + wrow + mt * 16 + gid) * DIM + nc + c;
                *(float2*)(out + r0)           = v0;
                *(float2*)(out + r0 + 8 * DIM) = v1;
            }
        }
    }
}

extern "C" void kernel_launch(void* const* d_in, const int* in_sizes, int n_in,
                              void* d_out, int out_size) {
    // metadata order: x, q_state, Wq, bq, Wk, bk, Wv, bv, Wo, bo
    const float* x  = (const float*)d_in[0];
    const float* Wv = (const float*)d_in[6];
    const float* bv = (const float*)d_in[7];
    const float* Wo = (const float*)d_in[8];
    const float* bo = (const float*)d_in[9];
    float* out = (float*)d_out;

    const int n_rows = in_sizes[0] / DIM;      // 65536
    const int grid   = n_rows / TILE_M;        // 512

    convert_weights_kernel<<<384, 256>>>(Wv, Wo);

    cudaFuncSetAttribute(pooling_retriever_kernel,
                         cudaFuncAttributeMaxDynamicSharedMemorySize, SMEM_BYTES);
    pooling_retriever_kernel<<<grid, NTHREADS, SMEM_BYTES>>>(x, bv, bo, out);
}

// round 7
// speedup vs baseline: 1.2135x; 1.1799x over previous
#include <cuda_runtime.h>
#include <cstdint>

// out = (x @ Wv.T + bv) @ Wo.T + bo   (softmax over singleton axis == 1)
// R5: x never touches smem. A-fragments loaded as coalesced LDG.128 straight
// from GMEM using a k-permutation baked into the pre-permuted weight layout
// (k-permutation inside each 8-wide MMA step is free if A and B agree).
// Stage-1 accumulators feed stage-2 A-frags directly in registers (k-remap),
// so T never touches smem either. Only W chunks go through smem
// (frag-order, cp.async depth-2, conflict-free LDS.128).

#define DIM      768
#define HH       64
#define TILE_M   128
#define NTHREADS 256                      // 8 warps, m16 rows each
#define WCH      (8 * 32 * 20)            // 5120 words per W chunk (frag order)
#define SMEM_WORDS (2 * WCH + DIM + HH)
#define SMEM_BYTES (SMEM_WORDS * 4)       // ~44 KB
#define NCH1     12
#define NCH      24

__device__ uint32_t g_Wfrag[NCH * WCH];   // 480 KB, L2-resident

__device__ __forceinline__ uint32_t f2tf32(float f) {
    uint32_t r;
    asm("cvt.rna.tf32.f32 %0, %1;" : "=r"(r) : "f"(f));
    return r;
}

__device__ __forceinline__ void cp16(void* sdst, const void* gsrc) {
    uint32_t s = (uint32_t)__cvta_generic_to_shared(sdst);
    asm volatile("cp.async.ca.shared.global [%0], [%1], 16;\n" :: "r"(s), "l"(gsrc));
}

__device__ __forceinline__ void mma8(float d[4], const uint32_t a[4], uint32_t b0, uint32_t b1) {
    asm volatile(
        "mma.sync.aligned.m16n8k8.row.col.f32.tf32.tf32.f32 "
        "{%0,%1,%2,%3}, {%4,%5,%6,%7}, {%8,%9}, {%0,%1,%2,%3};\n"
        : "+f"(d[0]), "+f"(d[1]), "+f"(d[2]), "+f"(d[3])
        : "r"(a[0]), "r"(a[1]), "r"(a[2]), "r"(a[3]), "r"(b0), "r"(b1));
}

// Prologue: permute Wv/Wo into per-lane fragment order with the SAME
// k-permutation the main kernel's A-side uses.
// word layout: [(c*8+nb)*32 + lane]*20 + w,  w in 0..15, lane stride 20 (80B).
// stage 1 (c<12):  p=w>>2, hi=(w>>1)&1, j=w&1 -> k = 16p + 4*t4 + 2*hi + j
// stage 2 (c>=12): s=2*(w>>2)+((w>>1)&1), j=w&1 -> k = 8s + 2*t4 + j
__global__ void convert_weights_kernel(const float* __restrict__ Wv,
                                       const float* __restrict__ Wo) {
    int idx = blockIdx.x * blockDim.x + threadIdx.x;   // 24*8*32*16 = 98304
    if (idx >= NCH * 8 * 32 * 16) return;
    int w  = idx & 15;
    int l  = (idx >> 4) & 31;
    int nb = (idx >> 9) & 7;
    int c  = idx >> 12;
    int gid = l >> 2, t4 = l & 3;
    int p  = w >> 2, hi = (w >> 1) & 1, j = w & 1;
    int n  = nb * 8 + gid;
    float v;
    if (c < NCH1) {
        int kk = p * 16 + 4 * t4 + 2 * hi + j;
        v = Wv[(size_t)n * DIM + c * 64 + kk];                   // Wv [64][768]
    } else {
        int s  = 2 * p + hi;
        int kk = s * 8 + 2 * t4 + j;
        v = Wo[(size_t)((c - NCH1) * 64 + n) * HH + kk];         // Wo [768][64]
    }
    g_Wfrag[((size_t)(c * 8 + nb) * 32 + l) * 20 + w] = f2tf32(v);
}

__global__ __launch_bounds__(NTHREADS, 2)
void pooling_retriever_kernel(const float* __restrict__ x,
                              const float* __restrict__ bv,
                              const float* __restrict__ bo,
                              float* __restrict__ out) {
    extern __shared__ uint32_t smem[];
    uint32_t* Wsm  = smem;                          // 2 x WCH
    float* bo_s    = (float*)(smem + 2 * WCH);      // 768
    float* bv_s    = bo_s + DIM;                    // 64

    const int tid  = threadIdx.x;
    const int warp = tid >> 5;
    const int lane = tid & 31;
    const int gid  = lane >> 2;
    const int t4   = lane & 3;
    const int m0   = blockIdx.x * TILE_M;
    const int wrow = warp * 16;

    auto issue_w = [&](int k) {
        uint32_t* wb = Wsm + (k & 1) * WCH;
        const uint32_t* gsrc = g_Wfrag + (size_t)k * WCH;
        #pragma unroll
        for (int i = 0; i < 5; i++) {               // 5120 words = 1280 uint4
            int u = tid + i * NTHREADS;
            cp16(wb + u * 4, gsrc + u * 4);
        }
        asm volatile("cp.async.commit_group;\n");
    };

    issue_w(0);
    // preload biases once
    if (tid < HH) bv_s[tid] = bv[tid];
    #pragma unroll
    for (int i = 0; i < 3; i++) bo_s[tid + i * NTHREADS] = bo[tid + i * NTHREADS];

    // row base pointers for this thread's two rows (gid, gid+8)
    const float* xr0 = x + (size_t)(m0 + wrow + gid) * DIM + 4 * t4;
    const float* xr1 = xr0 + 8 * DIM;

    // ---------------- Stage 1: T = x @ Wv.T + bv  (acc in regs) ----------------
    float acc[8][4];
    #pragma unroll
    for (int nb = 0; nb < 8; nb++)
        #pragma unroll
        for (int i = 0; i < 4; i++) acc[nb][i] = 0.f;

    for (int k = 0; k < NCH1; k++) {
        __syncthreads();                  // compute k-1 done -> buffer (k+1)&1 free
        issue_w(k + 1);                   // k==11 prefetches first Wo chunk
        asm volatile("cp.async.wait_group 1;\n");
        __syncthreads();                  // W chunk k visible

        // front-batch all x loads for this chunk (8 independent LDG.128)
        float4 v0[4], v1[4];
        #pragma unroll
        for (int p = 0; p < 4; p++) {
            v0[p] = *(const float4*)(xr0 + k * 64 + 16 * p);
            v1[p] = *(const float4*)(xr1 + k * 64 + 16 * p);
        }

        const uint32_t* wb = Wsm + (k & 1) * WCH;
        #pragma unroll
        for (int p = 0; p < 4; p++) {
            uint32_t ae[4], ao[4];
            ae[0] = f2tf32(v0[p].x); ae[1] = f2tf32(v1[p].x);
            ae[2] = f2tf32(v0[p].y); ae[3] = f2tf32(v1[p].y);
            ao[0] = f2tf32(v0[p].z); ao[1] = f2tf32(v1[p].z);
            ao[2] = f2tf32(v0[p].w); ao[3] = f2tf32(v1[p].w);
            #pragma unroll
            for (int nb = 0; nb < 8; nb++) {
                uint4 B = *(const uint4*)(wb + (nb * 32 + lane) * 20 + p * 4);
                mma8(acc[nb], ae, B.x, B.y);
                mma8(acc[nb], ao, B.z, B.w);
            }
        }
    }

    // ---- T -> stage-2 A fragments entirely in registers (k-remap) ----
    // stage-2 k-window s covers T cols s*8 + 2*t4 + j  (j = reg pair slot)
    uint32_t ta[8][4];
    #pragma unroll
    for (int s = 0; s < 8; s++) {
        int c = s * 8 + 2 * t4;
        float b0 = bv_s[c], b1 = bv_s[c + 1];
        ta[s][0] = f2tf32(acc[s][0] + b0);   // (row gid,   k = c)
        ta[s][1] = f2tf32(acc[s][2] + b0);   // (row gid+8, k = c)
        ta[s][2] = f2tf32(acc[s][1] + b1);   // (row gid,   k = c+1)
        ta[s][3] = f2tf32(acc[s][3] + b1);   // (row gid+8, k = c+1)
    }

    // ---------------- Stage 2: out = T @ Wo.T + bo ----------------
    float* orow0 = out + (size_t)(m0 + wrow + gid) * DIM;
    for (int k = NCH1; k < NCH; k++) {
        const int nc = (k - NCH1) * 64;
        __syncthreads();                  // prev compute done -> buffer free
        if (k + 1 < NCH) {
            issue_w(k + 1);
            asm volatile("cp.async.wait_group 1;\n");
        } else {
            asm volatile("cp.async.wait_group 0;\n");
        }
        __syncthreads();                  // W chunk k visible

        const uint32_t* wb = Wsm + (k & 1) * WCH;
        #pragma unroll
        for (int nb = 0; nb < 8; nb++)
            #pragma unroll
            for (int i = 0; i < 4; i++) acc[nb][i] = 0.f;

        #pragma unroll
        for (int p = 0; p < 4; p++) {
            #pragma unroll
            for (int nb = 0; nb < 8; nb++) {
                uint4 B = *(const uint4*)(wb + (nb * 32 + lane) * 20 + p * 4);
                mma8(acc[nb], ta[2 * p],     B.x, B.y);
                mma8(acc[nb], ta[2 * p + 1], B.z, B.w);
            }
        }
        #pragma unroll
        for (int nb = 0; nb < 8; nb++) {
            int c = nb * 8 + 2 * t4;
            float b0 = bo_s[nc + c], b1 = bo_s[nc + c + 1];
            float2 u0 = make_float2(acc[nb][0] + b0, acc[nb][1] + b1);
            float2 u1 = make_float2(acc[nb][2] + b0, acc[nb][3] + b1);
            *(float2*)(orow0 + nc + c)           = u0;
            *(float2*)(orow0 + 8 * DIM + nc + c) = u1;
        }
    }
}

extern "C" void kernel_launch(void* const* d_in, const int* in_sizes, int n_in,
                              void* d_out, int out_size) {
    // metadata order: x, q_state, Wq, bq, Wk, bk, Wv, bv, Wo, bo
    const float* x  = (const float*)d_in[0];
    const float* Wv = (const float*)d_in[6];
    const float* bv = (const float*)d_in[7];
    const float* Wo = (const float*)d_in[8];
    const float* bo = (const float*)d_in[9];
    float* out = (float*)d_out;

    const int n_rows = in_sizes[0] / DIM;      // 65536
    const int grid   = n_rows / TILE_M;        // 512

    convert_weights_kernel<<<384, 256>>>(Wv, Wo);

    cudaFuncSetAttribute(pooling_retriever_kernel,
                         cudaFuncAttributeMaxDynamicSharedMemorySize, SMEM_BYTES);
    pooling_retriever_kernel<<<grid, NTHREADS, SMEM_BYTES>>>(x, bv, bo, out);
}